// round 1
// baseline (speedup 1.0000x reference)
#include <cuda_runtime.h>

#define NPTS 16384
#define KNB  16

// Scratch (no allocations allowed): node-projection buffer + knn indices.
__device__ __align__(16) float g_A[NPTS * 128];
__device__ int g_nbr[NPTS * KNB];

// ---------------------------------------------------------------------------
// KNN: brute force, one row per thread, candidates tiled through smem.
// d2 ordering identical to reference: sq_i + sq_j - 2*dot (sq_i constant kept
// for formula parity). Top-16 maintained as a sorted register list.
// ---------------------------------------------------------------------------
__global__ void __launch_bounds__(64) knn_kernel(const float* __restrict__ pos) {
    __shared__ float4 s_cand[1024];
    const int row = blockIdx.x * 64 + threadIdx.x;
    const float px = pos[row * 3 + 0];
    const float py = pos[row * 3 + 1];
    const float pz = pos[row * 3 + 2];
    const float sqi = px * px + py * py + pz * pz;

    float key[KNB];
    int   kid[KNB];
#pragma unroll
    for (int s = 0; s < KNB; ++s) { key[s] = 3.4e38f; kid[s] = 0; }

    for (int base = 0; base < NPTS; base += 1024) {
        __syncthreads();
        for (int jj = threadIdx.x; jj < 1024; jj += 64) {
            const int j = base + jj;
            const float cx = pos[j * 3 + 0];
            const float cy = pos[j * 3 + 1];
            const float cz = pos[j * 3 + 2];
            s_cand[jj] = make_float4(cx, cy, cz, cx * cx + cy * cy + cz * cz);
        }
        __syncthreads();
#pragma unroll 4
        for (int jj = 0; jj < 1024; ++jj) {
            const float4 c = s_cand[jj];
            const float dot = fmaf(px, c.x, fmaf(py, c.y, pz * c.z));
            const float d2  = fmaf(-2.f, dot, sqi + c.w);
            if (d2 < key[KNB - 1]) {
                key[KNB - 1] = d2; kid[KNB - 1] = base + jj;
#pragma unroll
                for (int s = KNB - 1; s > 0; --s) {
                    if (key[s] < key[s - 1]) {
                        const float tk = key[s]; key[s] = key[s - 1]; key[s - 1] = tk;
                        const int   ti = kid[s]; kid[s] = kid[s - 1]; kid[s - 1] = ti;
                    }
                }
            }
        }
    }
#pragma unroll
    for (int s = 0; s < KNB; ++s) g_nbr[row * KNB + s] = kid[s];
}

// ---------------------------------------------------------------------------
// Node projection: A[n] = x[n] @ Wa[:CIN] + ba  (the x_j part of the edge MLP
// first linear depends only on the source node -> computed once per node).
// FIRST layer consumes concat(pos, normal) on the fly.
// ---------------------------------------------------------------------------
template <int CIN, int C, bool FIRST>
__global__ void proj_kernel(const float* __restrict__ x,
                            const float* __restrict__ pos,
                            const float* __restrict__ normal,
                            const float* __restrict__ Wa,
                            const float* __restrict__ ba) {
    const int idx = blockIdx.x * blockDim.x + threadIdx.x;
    if (idx >= NPTS * C) return;
    const int n = idx / C;
    const int c = idx - n * C;
    float acc = ba[c];
#pragma unroll
    for (int k = 0; k < CIN; ++k) {
        float xv;
        if (FIRST) xv = (k < 3) ? pos[n * 3 + k] : normal[n * 3 + (k - 3)];
        else       xv = x[n * CIN + k];
        acc = fmaf(xv, Wa[k * C + c], acc);
    }
    g_A[idx] = acc;
}

// ---------------------------------------------------------------------------
// Fused edge kernel per conv layer:
//  phase 1: H[e][c] = A[nbr_e] + rel_e @ Wa[rel rows]
//  phase 2: per-edge GroupNorm (group size 8) + gamma/beta + relu -> smem H^T
//  phase 3: 16xC x CxC mini-GEMM vs smem-resident Wb, max over edges,
//           +bias, relu, store.
// Block = 2*C threads, processes NPB nodes reusing smem Wb.
// ---------------------------------------------------------------------------
template <int C, int G, int NPB>
__global__ void __launch_bounds__(2 * C) edge_kernel(
    const float* __restrict__ pos,
    const float* __restrict__ Wa, int cin_node,
    const float* __restrict__ gmm, const float* __restrict__ bta,
    const float* __restrict__ Wb,  const float* __restrict__ bb,
    float* __restrict__ out) {
    constexpr int B  = 2 * C;
    constexpr int HS = 20;  // H^T row stride (floats), 16B-aligned rows
    extern __shared__ float smem[];
    float* s_Wb   = smem;                // C*C
    float* s_H    = s_Wb + C * C;        // C*HS
    float* s_Wrel = s_H + C * HS;        // 3*C
    float* s_g    = s_Wrel + 3 * C;      // C
    float* s_b    = s_g + C;             // C

    const int t = threadIdx.x;
    for (int i = t; i < C * C; i += B) s_Wb[i] = Wb[i];
    for (int i = t; i < 3 * C; i += B) s_Wrel[i] = Wa[cin_node * C + i];
    for (int i = t; i < C; i += B) { s_g[i] = gmm[i]; s_b[i] = bta[i]; }
    __syncthreads();

    const int e  = t & 15;        // edge index for phase 1/2
    const int g  = t >> 4;        // channel group (0..G-1)
    const int et = t & 3;         // edge tile (4 edges) for phase 3
    const int c2 = (t >> 2) * 2;  // output channel pair for phase 3

    for (int s = 0; s < NPB; ++s) {
        const int i = blockIdx.x * NPB + s;
        // ---- phase 1 + 2 : build normalized H^T in smem ----
        {
            const int j = g_nbr[i * KNB + e];
            const float rx = pos[j * 3 + 0] - pos[i * 3 + 0];
            const float ry = pos[j * 3 + 1] - pos[i * 3 + 1];
            const float rz = pos[j * 3 + 2] - pos[i * 3 + 2];
            const int c0 = g * 8;
            const float* Ar = g_A + j * C + c0;
            const float4 a0 = *reinterpret_cast<const float4*>(Ar);
            const float4 a1 = *reinterpret_cast<const float4*>(Ar + 4);
            float h[8] = {a0.x, a0.y, a0.z, a0.w, a1.x, a1.y, a1.z, a1.w};
            float sum = 0.f;
#pragma unroll
            for (int cc = 0; cc < 8; ++cc) {
                const int c = c0 + cc;
                h[cc] = h[cc] + rx * s_Wrel[c] + ry * s_Wrel[C + c] + rz * s_Wrel[2 * C + c];
                sum += h[cc];
            }
            const float mean = sum * 0.125f;
            float vs = 0.f;
#pragma unroll
            for (int cc = 0; cc < 8; ++cc) { const float d = h[cc] - mean; vs = fmaf(d, d, vs); }
            const float inv = rsqrtf(fmaf(vs, 0.125f, 1e-5f));
#pragma unroll
            for (int cc = 0; cc < 8; ++cc) {
                const int c = c0 + cc;
                const float v = fmaf((h[cc] - mean) * inv, s_g[c], s_b[c]);
                s_H[c * HS + e] = fmaxf(v, 0.f);
            }
        }
        __syncthreads();
        // ---- phase 3 : mini-GEMM + max over edges ----
        {
            float a00 = 0, a01 = 0, a10 = 0, a11 = 0;
            float a20 = 0, a21 = 0, a30 = 0, a31 = 0;
#pragma unroll 8
            for (int c = 0; c < C; ++c) {
                const float4 h4 = *reinterpret_cast<const float4*>(&s_H[c * HS + et * 4]);
                const float2 w2 = *reinterpret_cast<const float2*>(&s_Wb[c * C + c2]);
                a00 = fmaf(h4.x, w2.x, a00); a01 = fmaf(h4.x, w2.y, a01);
                a10 = fmaf(h4.y, w2.x, a10); a11 = fmaf(h4.y, w2.y, a11);
                a20 = fmaf(h4.z, w2.x, a20); a21 = fmaf(h4.z, w2.y, a21);
                a30 = fmaf(h4.w, w2.x, a30); a31 = fmaf(h4.w, w2.y, a31);
            }
            float m0 = fmaxf(fmaxf(a00, a10), fmaxf(a20, a30));
            float m1 = fmaxf(fmaxf(a01, a11), fmaxf(a21, a31));
            m0 = fmaxf(m0, __shfl_xor_sync(0xffffffffu, m0, 1));
            m0 = fmaxf(m0, __shfl_xor_sync(0xffffffffu, m0, 2));
            m1 = fmaxf(m1, __shfl_xor_sync(0xffffffffu, m1, 1));
            m1 = fmaxf(m1, __shfl_xor_sync(0xffffffffu, m1, 2));
            if (et == 0) {
                out[i * C + c2]     = fmaxf(m0 + bb[c2], 0.f);
                out[i * C + c2 + 1] = fmaxf(m1 + bb[c2 + 1], 0.f);
            }
        }
        __syncthreads();
    }
}

// ---------------------------------------------------------------------------
extern "C" void kernel_launch(void* const* d_in, const int* in_sizes, int n_in,
                              void* d_out, int out_size) {
    const float* pos    = (const float*)d_in[0];
    const float* normal = (const float*)d_in[1];
    const float* W1a = (const float*)d_in[2];
    const float* b1a = (const float*)d_in[3];
    const float* g1  = (const float*)d_in[4];
    const float* be1 = (const float*)d_in[5];
    const float* W1b = (const float*)d_in[6];
    const float* b1b = (const float*)d_in[7];
    const float* W2a = (const float*)d_in[8];
    const float* b2a = (const float*)d_in[9];
    const float* g2  = (const float*)d_in[10];
    const float* be2 = (const float*)d_in[11];
    const float* W2b = (const float*)d_in[12];
    const float* b2b = (const float*)d_in[13];
    const float* W3a = (const float*)d_in[14];
    const float* b3a = (const float*)d_in[15];
    const float* g3  = (const float*)d_in[16];
    const float* be3 = (const float*)d_in[17];
    const float* W3b = (const float*)d_in[18];
    const float* b3b = (const float*)d_in[19];

    float* out = (float*)d_out;
    float* h1 = out;                 // [N,64]
    float* h2 = out + NPTS * 64;     // [N,64]
    float* h3 = out + NPTS * 128;    // [N,128]

    const int SMEM64  = (64 * 64 + 64 * 20 + 3 * 64 + 2 * 64) * 4;     // 22784 B
    const int SMEM128 = (128 * 128 + 128 * 20 + 3 * 128 + 2 * 128) * 4; // 78336 B
    cudaFuncSetAttribute((const void*)edge_kernel<64, 8, 8>,
                         cudaFuncAttributeMaxDynamicSharedMemorySize, SMEM64);
    cudaFuncSetAttribute((const void*)edge_kernel<128, 16, 8>,
                         cudaFuncAttributeMaxDynamicSharedMemorySize, SMEM128);

    knn_kernel<<<NPTS / 64, 64>>>(pos);

    // conv1: Linear(9,64) -> GN(8) -> ReLU -> Linear(64,64) -> max -> ReLU
    proj_kernel<6, 64, true><<<(NPTS * 64) / 256, 256>>>(nullptr, pos, normal, W1a, b1a);
    edge_kernel<64, 8, 8><<<NPTS / 8, 128, SMEM64>>>(pos, W1a, 6, g1, be1, W1b, b1b, h1);

    // conv2: Linear(67,64) -> GN(8) -> ReLU -> Linear(64,64) -> max -> ReLU
    proj_kernel<64, 64, false><<<(NPTS * 64) / 256, 256>>>(h1, nullptr, nullptr, W2a, b2a);
    edge_kernel<64, 8, 8><<<NPTS / 8, 128, SMEM64>>>(pos, W2a, 64, g2, be2, W2b, b2b, h2);

    // conv3: Linear(67,128) -> GN(16) -> ReLU -> Linear(128,128) -> max -> ReLU
    proj_kernel<64, 128, false><<<(NPTS * 128) / 256, 256>>>(h2, nullptr, nullptr, W3a, b3a);
    edge_kernel<128, 16, 8><<<NPTS / 8, 256, SMEM128>>>(pos, W3a, 64, g3, be3, W3b, b3b, h3);
}

// round 2
// speedup vs baseline: 1.1468x; 1.1468x over previous
#include <cuda_runtime.h>

#define NPTS 16384
#define KNB  16
#define KCHUNKS 2
#define CH (NPTS / KCHUNKS)

// Scratch (no allocations allowed).
__device__ __align__(16) float g_A[NPTS * 128];
__device__ int g_nbr[NPTS * KNB];
__device__ unsigned long long g_part[KCHUNKS * NPTS * KNB];

// ---------------------------------------------------------------------------
// Max-replace top-16: evict the slot equal to cached max, recompute max via
// FMNMX tree. Low depth (~60cyc) vs serial sorted insertion (~240cyc).
// ---------------------------------------------------------------------------
__device__ __forceinline__ void insert16(float d2, int j, float key[KNB],
                                         int kid[KNB], float& kmax, bool ins) {
    bool found = !ins;
#pragma unroll
    for (int s = 0; s < KNB; ++s) {
        const bool m = (!found) && (key[s] == kmax);
        if (m) { key[s] = d2; kid[s] = j; }
        found = found || m;
    }
    // 15-FMNMX max tree
    float a0 = fmaxf(key[0], key[1]),   a1 = fmaxf(key[2], key[3]);
    float a2 = fmaxf(key[4], key[5]),   a3 = fmaxf(key[6], key[7]);
    float a4 = fmaxf(key[8], key[9]),   a5 = fmaxf(key[10], key[11]);
    float a6 = fmaxf(key[12], key[13]), a7 = fmaxf(key[14], key[15]);
    float b0 = fmaxf(a0, a1), b1 = fmaxf(a2, a3);
    float b2 = fmaxf(a4, a5), b3 = fmaxf(a6, a7);
    kmax = fmaxf(fmaxf(b0, b1), fmaxf(b2, b3));
}

// ---------------------------------------------------------------------------
// KNN partial pass: each thread = (row, chunk); scans CH candidates through a
// smem tile keeping an unsorted top-16 (max-replace). Output packed u64
// (ordered d2 bits << 32 | idx) so the merge is exact incl. idx tie-break.
// d2 arithmetic identical to the R1-passing kernel.
// ---------------------------------------------------------------------------
__global__ void __launch_bounds__(128) knn_part_kernel(const float* __restrict__ pos) {
    __shared__ float4 s_cand[1024];
    const int row   = blockIdx.x * 128 + threadIdx.x;
    const int chunk = blockIdx.y;
    const int cbase = chunk * CH;

    const float px = pos[row * 3 + 0];
    const float py = pos[row * 3 + 1];
    const float pz = pos[row * 3 + 2];
    const float sqi = px * px + py * py + pz * pz;

    float key[KNB];
    int   kid[KNB];
#pragma unroll
    for (int s = 0; s < KNB; ++s) { key[s] = 3.4e38f; kid[s] = 0; }
    float kmax = 3.4e38f;

    for (int tile = 0; tile < CH / 1024; ++tile) {
        const int tbase = cbase + tile * 1024;
        __syncthreads();
        for (int jj = threadIdx.x; jj < 1024; jj += 128) {
            const int j = tbase + jj;
            const float cx = pos[j * 3 + 0];
            const float cy = pos[j * 3 + 1];
            const float cz = pos[j * 3 + 2];
            s_cand[jj] = make_float4(cx, cy, cz, cx * cx + cy * cy + cz * cz);
        }
        __syncthreads();
        if (tile == 0) {
            // warm region: insertion near-certain -> branchless body
            for (int jj = 0; jj < 1024; ++jj) {
                const float4 c = s_cand[jj];
                const float dot = fmaf(px, c.x, fmaf(py, c.y, pz * c.z));
                const float d2  = fmaf(-2.f, dot, sqi + c.w);
                insert16(d2, tbase + jj, key, kid, kmax, d2 < kmax);
            }
        } else {
#pragma unroll 4
            for (int jj = 0; jj < 1024; ++jj) {
                const float4 c = s_cand[jj];
                const float dot = fmaf(px, c.x, fmaf(py, c.y, pz * c.z));
                const float d2  = fmaf(-2.f, dot, sqi + c.w);
                if (d2 < kmax) insert16(d2, tbase + jj, key, kid, kmax, true);
            }
        }
    }
#pragma unroll
    for (int s = 0; s < KNB; ++s) {
        unsigned u = __float_as_uint(key[s]);
        u = (u & 0x80000000u) ? ~u : (u | 0x80000000u);
        g_part[((size_t)chunk * NPTS + row) * KNB + s] =
            ((unsigned long long)u << 32) | (unsigned)kid[s];
    }
}

// ---------------------------------------------------------------------------
// Merge KCHUNKS partial lists per row -> final 16 neighbor indices.
// Packed u64 compare => exact d2 ordering with lower-index tie-break.
// ---------------------------------------------------------------------------
__global__ void knn_merge_kernel() {
    const int r = blockIdx.x * blockDim.x + threadIdx.x;
    unsigned long long best[KNB];
#pragma unroll
    for (int s = 0; s < KNB; ++s) best[s] = g_part[(size_t)r * KNB + s];

    unsigned long long bmax = best[0];
#pragma unroll
    for (int s = 1; s < KNB; ++s) bmax = best[s] > bmax ? best[s] : bmax;

#pragma unroll 1
    for (int ch = 1; ch < KCHUNKS; ++ch) {
#pragma unroll
        for (int c = 0; c < KNB; ++c) {
            const unsigned long long v = g_part[((size_t)ch * NPTS + r) * KNB + c];
            if (v < bmax) {
                bool found = false;
#pragma unroll
                for (int s = 0; s < KNB; ++s) {
                    const bool m = (!found) && (best[s] == bmax);
                    if (m) best[s] = v;
                    found = found || m;
                }
                bmax = best[0];
#pragma unroll
                for (int s = 1; s < KNB; ++s) bmax = best[s] > bmax ? best[s] : bmax;
            }
        }
    }
#pragma unroll
    for (int s = 0; s < KNB; ++s)
        g_nbr[r * KNB + s] = (int)(best[s] & 0xFFFFFFFFull);
}

// ---------------------------------------------------------------------------
// Node projection: A[n] = x[n] @ Wa[:CIN] + ba. Wa cached in smem, 4 channels
// per thread via float4 (R1 version was L1-bound on Wa re-reads).
// ---------------------------------------------------------------------------
template <int CIN, int C, bool FIRST>
__global__ void __launch_bounds__(128) proj_kernel(const float* __restrict__ x,
                                                   const float* __restrict__ pos,
                                                   const float* __restrict__ nrm,
                                                   const float* __restrict__ Wa,
                                                   const float* __restrict__ ba) {
    constexpr int TPN = C / 4;             // threads per node
    __shared__ __align__(16) float sW[CIN * C];
    __shared__ __align__(16) float sb[C];
    const int t = threadIdx.x;
    for (int i = t; i < CIN * C; i += 128) sW[i] = Wa[i];
    for (int i = t; i < C; i += 128) sb[i] = ba[i];
    __syncthreads();

    const int n  = blockIdx.x * (128 / TPN) + t / TPN;
    const int c0 = (t % TPN) * 4;
    float4 acc = *reinterpret_cast<const float4*>(&sb[c0]);
#pragma unroll
    for (int k = 0; k < CIN; ++k) {
        float xv;
        if (FIRST) xv = (k < 3) ? pos[n * 3 + k] : nrm[n * 3 + (k - 3)];
        else       xv = x[n * CIN + k];
        const float4 w = *reinterpret_cast<const float4*>(&sW[k * C + c0]);
        acc.x = fmaf(xv, w.x, acc.x);
        acc.y = fmaf(xv, w.y, acc.y);
        acc.z = fmaf(xv, w.z, acc.z);
        acc.w = fmaf(xv, w.w, acc.w);
    }
    *reinterpret_cast<float4*>(&g_A[n * C + c0]) = acc;
}

// ---------------------------------------------------------------------------
// Fused edge kernel (unchanged from R1-passing version).
// ---------------------------------------------------------------------------
template <int C, int G, int NPB>
__global__ void __launch_bounds__(2 * C) edge_kernel(
    const float* __restrict__ pos,
    const float* __restrict__ Wa, int cin_node,
    const float* __restrict__ gmm, const float* __restrict__ bta,
    const float* __restrict__ Wb,  const float* __restrict__ bb,
    float* __restrict__ out) {
    constexpr int B  = 2 * C;
    constexpr int HS = 20;
    extern __shared__ float smem[];
    float* s_Wb   = smem;
    float* s_H    = s_Wb + C * C;
    float* s_Wrel = s_H + C * HS;
    float* s_g    = s_Wrel + 3 * C;
    float* s_b    = s_g + C;

    const int t = threadIdx.x;
    for (int i = t; i < C * C; i += B) s_Wb[i] = Wb[i];
    for (int i = t; i < 3 * C; i += B) s_Wrel[i] = Wa[cin_node * C + i];
    for (int i = t; i < C; i += B) { s_g[i] = gmm[i]; s_b[i] = bta[i]; }
    __syncthreads();

    const int e  = t & 15;
    const int g  = t >> 4;
    const int et = t & 3;
    const int c2 = (t >> 2) * 2;

    for (int s = 0; s < NPB; ++s) {
        const int i = blockIdx.x * NPB + s;
        {
            const int j = g_nbr[i * KNB + e];
            const float rx = pos[j * 3 + 0] - pos[i * 3 + 0];
            const float ry = pos[j * 3 + 1] - pos[i * 3 + 1];
            const float rz = pos[j * 3 + 2] - pos[i * 3 + 2];
            const int c0 = g * 8;
            const float* Ar = g_A + j * C + c0;
            const float4 a0 = *reinterpret_cast<const float4*>(Ar);
            const float4 a1 = *reinterpret_cast<const float4*>(Ar + 4);
            float h[8] = {a0.x, a0.y, a0.z, a0.w, a1.x, a1.y, a1.z, a1.w};
            float sum = 0.f;
#pragma unroll
            for (int cc = 0; cc < 8; ++cc) {
                const int c = c0 + cc;
                h[cc] = h[cc] + rx * s_Wrel[c] + ry * s_Wrel[C + c] + rz * s_Wrel[2 * C + c];
                sum += h[cc];
            }
            const float mean = sum * 0.125f;
            float vs = 0.f;
#pragma unroll
            for (int cc = 0; cc < 8; ++cc) { const float d = h[cc] - mean; vs = fmaf(d, d, vs); }
            const float inv = rsqrtf(fmaf(vs, 0.125f, 1e-5f));
#pragma unroll
            for (int cc = 0; cc < 8; ++cc) {
                const int c = c0 + cc;
                const float v = fmaf((h[cc] - mean) * inv, s_g[c], s_b[c]);
                s_H[c * HS + e] = fmaxf(v, 0.f);
            }
        }
        __syncthreads();
        {
            float a00 = 0, a01 = 0, a10 = 0, a11 = 0;
            float a20 = 0, a21 = 0, a30 = 0, a31 = 0;
#pragma unroll 8
            for (int c = 0; c < C; ++c) {
                const float4 h4 = *reinterpret_cast<const float4*>(&s_H[c * HS + et * 4]);
                const float2 w2 = *reinterpret_cast<const float2*>(&s_Wb[c * C + c2]);
                a00 = fmaf(h4.x, w2.x, a00); a01 = fmaf(h4.x, w2.y, a01);
                a10 = fmaf(h4.y, w2.x, a10); a11 = fmaf(h4.y, w2.y, a11);
                a20 = fmaf(h4.z, w2.x, a20); a21 = fmaf(h4.z, w2.y, a21);
                a30 = fmaf(h4.w, w2.x, a30); a31 = fmaf(h4.w, w2.y, a31);
            }
            float m0 = fmaxf(fmaxf(a00, a10), fmaxf(a20, a30));
            float m1 = fmaxf(fmaxf(a01, a11), fmaxf(a21, a31));
            m0 = fmaxf(m0, __shfl_xor_sync(0xffffffffu, m0, 1));
            m0 = fmaxf(m0, __shfl_xor_sync(0xffffffffu, m0, 2));
            m1 = fmaxf(m1, __shfl_xor_sync(0xffffffffu, m1, 1));
            m1 = fmaxf(m1, __shfl_xor_sync(0xffffffffu, m1, 2));
            if (et == 0) {
                out[i * C + c2]     = fmaxf(m0 + bb[c2], 0.f);
                out[i * C + c2 + 1] = fmaxf(m1 + bb[c2 + 1], 0.f);
            }
        }
        __syncthreads();
    }
}

// ---------------------------------------------------------------------------
extern "C" void kernel_launch(void* const* d_in, const int* in_sizes, int n_in,
                              void* d_out, int out_size) {
    const float* pos    = (const float*)d_in[0];
    const float* normal = (const float*)d_in[1];
    const float* W1a = (const float*)d_in[2];
    const float* b1a = (const float*)d_in[3];
    const float* g1  = (const float*)d_in[4];
    const float* be1 = (const float*)d_in[5];
    const float* W1b = (const float*)d_in[6];
    const float* b1b = (const float*)d_in[7];
    const float* W2a = (const float*)d_in[8];
    const float* b2a = (const float*)d_in[9];
    const float* g2  = (const float*)d_in[10];
    const float* be2 = (const float*)d_in[11];
    const float* W2b = (const float*)d_in[12];
    const float* b2b = (const float*)d_in[13];
    const float* W3a = (const float*)d_in[14];
    const float* b3a = (const float*)d_in[15];
    const float* g3  = (const float*)d_in[16];
    const float* be3 = (const float*)d_in[17];
    const float* W3b = (const float*)d_in[18];
    const float* b3b = (const float*)d_in[19];

    float* out = (float*)d_out;
    float* h1 = out;
    float* h2 = out + NPTS * 64;
    float* h3 = out + NPTS * 128;

    const int SMEM64  = (64 * 64 + 64 * 20 + 3 * 64 + 2 * 64) * 4;
    const int SMEM128 = (128 * 128 + 128 * 20 + 3 * 128 + 2 * 128) * 4;
    cudaFuncSetAttribute((const void*)edge_kernel<64, 8, 8>,
                         cudaFuncAttributeMaxDynamicSharedMemorySize, SMEM64);
    cudaFuncSetAttribute((const void*)edge_kernel<128, 16, 8>,
                         cudaFuncAttributeMaxDynamicSharedMemorySize, SMEM128);

    knn_part_kernel<<<dim3(NPTS / 128, KCHUNKS), 128>>>(pos);
    knn_merge_kernel<<<NPTS / 256, 256>>>();

    proj_kernel<6, 64, true><<<NPTS / 8, 128>>>(nullptr, pos, normal, W1a, b1a);
    edge_kernel<64, 8, 8><<<NPTS / 8, 128, SMEM64>>>(pos, W1a, 6, g1, be1, W1b, b1b, h1);

    proj_kernel<64, 64, false><<<NPTS / 8, 128>>>(h1, nullptr, nullptr, W2a, b2a);
    edge_kernel<64, 8, 8><<<NPTS / 8, 128, SMEM64>>>(pos, W2a, 64, g2, be2, W2b, b2b, h2);

    proj_kernel<64, 128, false><<<NPTS / 4, 128>>>(h2, nullptr, nullptr, W3a, b3a);
    edge_kernel<128, 16, 8><<<NPTS / 8, 256, SMEM128>>>(pos, W3a, 64, g3, be3, W3b, b3b, h3);
}

// round 3
// speedup vs baseline: 1.4297x; 1.2466x over previous
#include <cuda_runtime.h>

#define NPTS 16384
#define KNB  16
#define KCHUNKS 2
#define CH (NPTS / KCHUNKS)

// Scratch (no allocations allowed).
__device__ __align__(16) float g_A[NPTS * 128];
__device__ int g_nbr[NPTS * KNB];
__device__ unsigned long long g_part[KCHUNKS * NPTS * KNB];

// ---------------------------------------------------------------------------
// Max-replace top-16 (unchanged from R2-passing version).
// ---------------------------------------------------------------------------
__device__ __forceinline__ void insert16(float d2, int j, float key[KNB],
                                         int kid[KNB], float& kmax, bool ins) {
    bool found = !ins;
#pragma unroll
    for (int s = 0; s < KNB; ++s) {
        const bool m = (!found) && (key[s] == kmax);
        if (m) { key[s] = d2; kid[s] = j; }
        found = found || m;
    }
    float a0 = fmaxf(key[0], key[1]),   a1 = fmaxf(key[2], key[3]);
    float a2 = fmaxf(key[4], key[5]),   a3 = fmaxf(key[6], key[7]);
    float a4 = fmaxf(key[8], key[9]),   a5 = fmaxf(key[10], key[11]);
    float a6 = fmaxf(key[12], key[13]), a7 = fmaxf(key[14], key[15]);
    float b0 = fmaxf(a0, a1), b1 = fmaxf(a2, a3);
    float b2 = fmaxf(a4, a5), b3 = fmaxf(a6, a7);
    kmax = fmaxf(fmaxf(b0, b1), fmaxf(b2, b3));
}

__global__ void __launch_bounds__(128) knn_part_kernel(const float* __restrict__ pos) {
    __shared__ float4 s_cand[1024];
    const int row   = blockIdx.x * 128 + threadIdx.x;
    const int chunk = blockIdx.y;
    const int cbase = chunk * CH;

    const float px = pos[row * 3 + 0];
    const float py = pos[row * 3 + 1];
    const float pz = pos[row * 3 + 2];
    const float sqi = px * px + py * py + pz * pz;

    float key[KNB];
    int   kid[KNB];
#pragma unroll
    for (int s = 0; s < KNB; ++s) { key[s] = 3.4e38f; kid[s] = 0; }
    float kmax = 3.4e38f;

    for (int tile = 0; tile < CH / 1024; ++tile) {
        const int tbase = cbase + tile * 1024;
        __syncthreads();
        for (int jj = threadIdx.x; jj < 1024; jj += 128) {
            const int j = tbase + jj;
            const float cx = pos[j * 3 + 0];
            const float cy = pos[j * 3 + 1];
            const float cz = pos[j * 3 + 2];
            s_cand[jj] = make_float4(cx, cy, cz, cx * cx + cy * cy + cz * cz);
        }
        __syncthreads();
        if (tile == 0) {
            for (int jj = 0; jj < 1024; ++jj) {
                const float4 c = s_cand[jj];
                const float dot = fmaf(px, c.x, fmaf(py, c.y, pz * c.z));
                const float d2  = fmaf(-2.f, dot, sqi + c.w);
                insert16(d2, tbase + jj, key, kid, kmax, d2 < kmax);
            }
        } else {
#pragma unroll 4
            for (int jj = 0; jj < 1024; ++jj) {
                const float4 c = s_cand[jj];
                const float dot = fmaf(px, c.x, fmaf(py, c.y, pz * c.z));
                const float d2  = fmaf(-2.f, dot, sqi + c.w);
                if (d2 < kmax) insert16(d2, tbase + jj, key, kid, kmax, true);
            }
        }
    }
#pragma unroll
    for (int s = 0; s < KNB; ++s) {
        unsigned u = __float_as_uint(key[s]);
        u = (u & 0x80000000u) ? ~u : (u | 0x80000000u);
        g_part[((size_t)chunk * NPTS + row) * KNB + s] =
            ((unsigned long long)u << 32) | (unsigned)kid[s];
    }
}

__global__ void knn_merge_kernel() {
    const int r = blockIdx.x * blockDim.x + threadIdx.x;
    unsigned long long best[KNB];
#pragma unroll
    for (int s = 0; s < KNB; ++s) best[s] = g_part[(size_t)r * KNB + s];

    unsigned long long bmax = best[0];
#pragma unroll
    for (int s = 1; s < KNB; ++s) bmax = best[s] > bmax ? best[s] : bmax;

#pragma unroll 1
    for (int ch = 1; ch < KCHUNKS; ++ch) {
#pragma unroll
        for (int c = 0; c < KNB; ++c) {
            const unsigned long long v = g_part[((size_t)ch * NPTS + r) * KNB + c];
            if (v < bmax) {
                bool found = false;
#pragma unroll
                for (int s = 0; s < KNB; ++s) {
                    const bool m = (!found) && (best[s] == bmax);
                    if (m) best[s] = v;
                    found = found || m;
                }
                bmax = best[0];
#pragma unroll
                for (int s = 1; s < KNB; ++s) bmax = best[s] > bmax ? best[s] : bmax;
            }
        }
    }
#pragma unroll
    for (int s = 0; s < KNB; ++s)
        g_nbr[r * KNB + s] = (int)(best[s] & 0xFFFFFFFFull);
}

// ---------------------------------------------------------------------------
// Node projection (unchanged from R2-passing version).
// ---------------------------------------------------------------------------
template <int CIN, int C, bool FIRST>
__global__ void __launch_bounds__(128) proj_kernel(const float* __restrict__ x,
                                                   const float* __restrict__ pos,
                                                   const float* __restrict__ nrm,
                                                   const float* __restrict__ Wa,
                                                   const float* __restrict__ ba) {
    constexpr int TPN = C / 4;
    __shared__ __align__(16) float sW[CIN * C];
    __shared__ __align__(16) float sb[C];
    const int t = threadIdx.x;
    for (int i = t; i < CIN * C; i += 128) sW[i] = Wa[i];
    for (int i = t; i < C; i += 128) sb[i] = ba[i];
    __syncthreads();

    const int n  = blockIdx.x * (128 / TPN) + t / TPN;
    const int c0 = (t % TPN) * 4;
    float4 acc = *reinterpret_cast<const float4*>(&sb[c0]);
#pragma unroll
    for (int k = 0; k < CIN; ++k) {
        float xv;
        if (FIRST) xv = (k < 3) ? pos[n * 3 + k] : nrm[n * 3 + (k - 3)];
        else       xv = x[n * CIN + k];
        const float4 w = *reinterpret_cast<const float4*>(&sW[k * C + c0]);
        acc.x = fmaf(xv, w.x, acc.x);
        acc.y = fmaf(xv, w.y, acc.y);
        acc.z = fmaf(xv, w.z, acc.z);
        acc.w = fmaf(xv, w.w, acc.w);
    }
    *reinterpret_cast<float4*>(&g_A[n * C + c0]) = acc;
}

// ---------------------------------------------------------------------------
// Fused edge kernel, R3: phase 3 register-tiled (4 edges x 8 channels per
// thread, one warp per node for C=64, two warps per node for C=128), nodes
// batched 4 at a time so every warp has a full tile and barriers drop 4x.
// ---------------------------------------------------------------------------
template <int C, int G, int NPB>
__global__ void __launch_bounds__(2 * C) edge_kernel(
    const float* __restrict__ pos,
    const float* __restrict__ Wa, int cin_node,
    const float* __restrict__ gmm, const float* __restrict__ bta,
    const float* __restrict__ Wb,  const float* __restrict__ bb,
    float* __restrict__ out) {
    constexpr int B  = 2 * C;
    constexpr int HS = 20;   // H^T row stride (floats)
    constexpr int NG = 4;    // nodes per batch
    extern __shared__ float smem[];
    float* s_Wb   = smem;                 // C*C
    float* s_H    = s_Wb + C * C;         // NG*C*HS
    float* s_Wrel = s_H + NG * C * HS;    // 3*C
    float* s_g    = s_Wrel + 3 * C;       // C
    float* s_b    = s_g + C;              // C
    float* s_bb   = s_b + C;              // C

    const int t = threadIdx.x;
    for (int i = t; i < C * C; i += B) s_Wb[i] = Wb[i];
    for (int i = t; i < 3 * C; i += B) s_Wrel[i] = Wa[cin_node * C + i];
    for (int i = t; i < C; i += B) { s_g[i] = gmm[i]; s_b[i] = bta[i]; s_bb[i] = bb[i]; }
    __syncthreads();

    const int e    = t & 15;
    const int g    = t >> 4;
    const int lane = t & 31;
    const int w    = t >> 5;
    const int et   = lane & 3;
    const int fi   = lane >> 2;
    const int q3   = (C == 128) ? (w >> 1) : w;             // node within batch
    const int f0   = ((C == 128) ? (w & 1) * 64 : 0) + fi * 8;

    for (int s0 = 0; s0 < NPB; s0 += NG) {
        // ---- phase 1 + 2 for NG nodes: normalized H^T into smem ----
#pragma unroll
        for (int q = 0; q < NG; ++q) {
            const int i = blockIdx.x * NPB + s0 + q;
            float* Hq = s_H + q * C * HS;
            const int j = g_nbr[i * KNB + e];
            const float rx = pos[j * 3 + 0] - pos[i * 3 + 0];
            const float ry = pos[j * 3 + 1] - pos[i * 3 + 1];
            const float rz = pos[j * 3 + 2] - pos[i * 3 + 2];
            const int c0 = g * 8;
            const float* Ar = g_A + j * C + c0;
            const float4 a0 = *reinterpret_cast<const float4*>(Ar);
            const float4 a1 = *reinterpret_cast<const float4*>(Ar + 4);
            float h[8] = {a0.x, a0.y, a0.z, a0.w, a1.x, a1.y, a1.z, a1.w};
            float sum = 0.f;
#pragma unroll
            for (int cc = 0; cc < 8; ++cc) {
                const int c = c0 + cc;
                h[cc] = h[cc] + rx * s_Wrel[c] + ry * s_Wrel[C + c] + rz * s_Wrel[2 * C + c];
                sum += h[cc];
            }
            const float mean = sum * 0.125f;
            float vs = 0.f;
#pragma unroll
            for (int cc = 0; cc < 8; ++cc) { const float d = h[cc] - mean; vs = fmaf(d, d, vs); }
            const float inv = rsqrtf(fmaf(vs, 0.125f, 1e-5f));
#pragma unroll
            for (int cc = 0; cc < 8; ++cc) {
                const int c = c0 + cc;
                const float v = fmaf((h[cc] - mean) * inv, s_g[c], s_b[c]);
                Hq[c * HS + e] = fmaxf(v, 0.f);
            }
        }
        __syncthreads();
        // ---- phase 3: warp-per-node mini-GEMM, 4x8 register tile ----
        {
            const int i = blockIdx.x * NPB + s0 + q3;
            const float* Hq = s_H + q3 * C * HS;
            float acc[4][8];
#pragma unroll
            for (int a = 0; a < 4; ++a)
#pragma unroll
                for (int f = 0; f < 8; ++f) acc[a][f] = 0.f;

#pragma unroll 4
            for (int c = 0; c < C; ++c) {
                const float4 h4 = *reinterpret_cast<const float4*>(&Hq[c * HS + et * 4]);
                const float4 wa = *reinterpret_cast<const float4*>(&s_Wb[c * C + f0]);
                const float4 wc = *reinterpret_cast<const float4*>(&s_Wb[c * C + f0 + 4]);
                const float he[4] = {h4.x, h4.y, h4.z, h4.w};
                const float wf[8] = {wa.x, wa.y, wa.z, wa.w, wc.x, wc.y, wc.z, wc.w};
#pragma unroll
                for (int a = 0; a < 4; ++a)
#pragma unroll
                    for (int f = 0; f < 8; ++f)
                        acc[a][f] = fmaf(he[a], wf[f], acc[a][f]);
            }
            float m[8];
#pragma unroll
            for (int f = 0; f < 8; ++f) {
                m[f] = fmaxf(fmaxf(acc[0][f], acc[1][f]), fmaxf(acc[2][f], acc[3][f]));
                m[f] = fmaxf(m[f], __shfl_xor_sync(0xffffffffu, m[f], 1));
                m[f] = fmaxf(m[f], __shfl_xor_sync(0xffffffffu, m[f], 2));
            }
            if (et == 0) {
                float4 r0, r1;
                r0.x = fmaxf(m[0] + s_bb[f0 + 0], 0.f);
                r0.y = fmaxf(m[1] + s_bb[f0 + 1], 0.f);
                r0.z = fmaxf(m[2] + s_bb[f0 + 2], 0.f);
                r0.w = fmaxf(m[3] + s_bb[f0 + 3], 0.f);
                r1.x = fmaxf(m[4] + s_bb[f0 + 4], 0.f);
                r1.y = fmaxf(m[5] + s_bb[f0 + 5], 0.f);
                r1.z = fmaxf(m[6] + s_bb[f0 + 6], 0.f);
                r1.w = fmaxf(m[7] + s_bb[f0 + 7], 0.f);
                *reinterpret_cast<float4*>(&out[i * C + f0])     = r0;
                *reinterpret_cast<float4*>(&out[i * C + f0 + 4]) = r1;
            }
        }
        __syncthreads();
    }
}

// ---------------------------------------------------------------------------
extern "C" void kernel_launch(void* const* d_in, const int* in_sizes, int n_in,
                              void* d_out, int out_size) {
    const float* pos    = (const float*)d_in[0];
    const float* normal = (const float*)d_in[1];
    const float* W1a = (const float*)d_in[2];
    const float* b1a = (const float*)d_in[3];
    const float* g1  = (const float*)d_in[4];
    const float* be1 = (const float*)d_in[5];
    const float* W1b = (const float*)d_in[6];
    const float* b1b = (const float*)d_in[7];
    const float* W2a = (const float*)d_in[8];
    const float* b2a = (const float*)d_in[9];
    const float* g2  = (const float*)d_in[10];
    const float* be2 = (const float*)d_in[11];
    const float* W2b = (const float*)d_in[12];
    const float* b2b = (const float*)d_in[13];
    const float* W3a = (const float*)d_in[14];
    const float* b3a = (const float*)d_in[15];
    const float* g3  = (const float*)d_in[16];
    const float* be3 = (const float*)d_in[17];
    const float* W3b = (const float*)d_in[18];
    const float* b3b = (const float*)d_in[19];

    float* out = (float*)d_out;
    float* h1 = out;
    float* h2 = out + NPTS * 64;
    float* h3 = out + NPTS * 128;

    const int SMEM64  = (64 * 64  + 4 * 64 * 20  + 3 * 64  + 3 * 64)  * 4;  // ~38.9KB
    const int SMEM128 = (128 * 128 + 4 * 128 * 20 + 3 * 128 + 3 * 128) * 4; // ~109.6KB
    cudaFuncSetAttribute((const void*)edge_kernel<64, 8, 8>,
                         cudaFuncAttributeMaxDynamicSharedMemorySize, SMEM64);
    cudaFuncSetAttribute((const void*)edge_kernel<128, 16, 8>,
                         cudaFuncAttributeMaxDynamicSharedMemorySize, SMEM128);

    knn_part_kernel<<<dim3(NPTS / 128, KCHUNKS), 128>>>(pos);
    knn_merge_kernel<<<NPTS / 256, 256>>>();

    proj_kernel<6, 64, true><<<NPTS / 8, 128>>>(nullptr, pos, normal, W1a, b1a);
    edge_kernel<64, 8, 8><<<NPTS / 8, 128, SMEM64>>>(pos, W1a, 6, g1, be1, W1b, b1b, h1);

    proj_kernel<64, 64, false><<<NPTS / 8, 128>>>(h1, nullptr, nullptr, W2a, b2a);
    edge_kernel<64, 8, 8><<<NPTS / 8, 128, SMEM64>>>(pos, W2a, 64, g2, be2, W2b, b2b, h2);

    proj_kernel<64, 128, false><<<NPTS / 4, 128>>>(h2, nullptr, nullptr, W3a, b3a);
    edge_kernel<128, 16, 8><<<NPTS / 8, 256, SMEM128>>>(pos, W3a, 64, g3, be3, W3b, b3b, h3);
}

// round 4
// speedup vs baseline: 2.2625x; 1.5825x over previous
#include <cuda_runtime.h>

#define NPTS 16384
#define KNB  16

// Scratch (no allocations allowed).
__device__ __align__(16) float g_A[NPTS * 128];
__device__ int g_nbr[NPTS * KNB];
__device__ __align__(16) float4 g_pos4[NPTS];

// ---------------------------------------------------------------------------
// Pack pos -> float4 (x,y,z,|p|^2) once; both sides of d2 use the same sq.
// ---------------------------------------------------------------------------
__global__ void pos4_kernel(const float* __restrict__ pos) {
    const int i = blockIdx.x * blockDim.x + threadIdx.x;
    const float x = pos[3 * i], y = pos[3 * i + 1], z = pos[3 * i + 2];
    g_pos4[i] = make_float4(x, y, z, x * x + y * y + z * z);
}

// ---------------------------------------------------------------------------
// Warp-cooperative bitonic helpers on packed u64 keys (asc = smaller d2 first,
// ties broken by lower index via low 32 bits).
// ---------------------------------------------------------------------------
__device__ __forceinline__ unsigned long long sort32(unsigned long long v, int lane) {
#pragma unroll
    for (int k = 2; k <= 32; k <<= 1) {
#pragma unroll
        for (int j = k >> 1; j > 0; j >>= 1) {
            const unsigned long long o = __shfl_xor_sync(0xffffffffu, v, j);
            const bool keepMin = (((lane & j) == 0) == ((lane & k) == 0));
            v = ((v < o) == keepMin) ? v : o;
        }
    }
    return v;
}

// a, b sorted ascending across lanes; returns the lowest 32 of the 64, sorted.
__device__ __forceinline__ unsigned long long merge_lower(unsigned long long a,
                                                          unsigned long long b,
                                                          int lane) {
    const unsigned long long br = __shfl_sync(0xffffffffu, b, 31 - lane);
    unsigned long long m = (a < br) ? a : br;   // bitonic sequence
#pragma unroll
    for (int j = 16; j > 0; j >>= 1) {
        const unsigned long long o = __shfl_xor_sync(0xffffffffu, m, j);
        const bool keepMin = ((lane & j) == 0);
        m = ((m < o) == keepMin) ? m : o;
    }
    return m;
}

__device__ __forceinline__ void flush_merge(unsigned long long& v,
                                            unsigned long long& kth,
                                            const unsigned long long* buf,
                                            int cnt, int lane) {
    __syncwarp();
    unsigned long long b0 = (lane < cnt) ? buf[lane] : ~0ull;
    b0 = sort32(b0, lane);
    if (cnt > 32) {
        unsigned long long b1 = (32 + lane < cnt) ? buf[32 + lane] : ~0ull;
        b1 = sort32(b1, lane);
        b0 = merge_lower(b0, b1, lane);
    }
    v = merge_lower(v, b0, lane);
    kth = __shfl_sync(0xffffffffu, v, 15);   // 16th-best = selection threshold
}

// ---------------------------------------------------------------------------
// KNN: one warp per row. 32 candidates per iteration, ballot-filtered into a
// per-warp smem buffer; rare warp-cooperative flush maintains sorted best-32.
// ---------------------------------------------------------------------------
#define WPB  16
#define TILE 1024

__global__ void __launch_bounds__(32 * WPB) knn_kernel() {
    __shared__ float4 s_cand[TILE];
    __shared__ unsigned long long s_buf[WPB][64];

    const int lane = threadIdx.x & 31;
    const int w    = threadIdx.x >> 5;
    const int row  = blockIdx.x * WPB + w;
    const float4 p = g_pos4[row];

    unsigned long long v   = ~0ull;  // sorted best-32 (lane l = l-th smallest)
    unsigned long long kth = ~0ull;  // 16th best key
    int bufcnt = 0;

    for (int base = 0; base < NPTS; base += TILE) {
        __syncthreads();
        for (int i = threadIdx.x; i < TILE; i += 32 * WPB) s_cand[i] = g_pos4[base + i];
        __syncthreads();
#pragma unroll 4
        for (int i = 0; i < TILE; i += 32) {
            const float4 c = s_cand[i + lane];
            const float dot = fmaf(p.x, c.x, fmaf(p.y, c.y, p.z * c.z));
            const float d2  = fmaf(-2.f, dot, p.w + c.w);
            unsigned u = __float_as_uint(d2);
            u = (u & 0x80000000u) ? ~u : (u | 0x80000000u);
            const unsigned long long key =
                ((unsigned long long)u << 32) | (unsigned)(base + i + lane);
            const bool pred = key < kth;
            const unsigned bal = __ballot_sync(0xffffffffu, pred);
            if (bal) {
                if (pred)
                    s_buf[w][bufcnt + __popc(bal & ((1u << lane) - 1u))] = key;
                bufcnt += __popc(bal);
                if (bufcnt > 32) {           // capacity 64: next iter adds <=32
                    flush_merge(v, kth, s_buf[w], bufcnt, lane);
                    bufcnt = 0;
                }
            }
        }
    }
    if (bufcnt) flush_merge(v, kth, s_buf[w], bufcnt, lane);
    if (lane < KNB) g_nbr[row * KNB + lane] = (int)(v & 0xFFFFFFFFull);
}

// ---------------------------------------------------------------------------
// Node projection (unchanged from R3-passing version).
// ---------------------------------------------------------------------------
template <int CIN, int C, bool FIRST>
__global__ void __launch_bounds__(128) proj_kernel(const float* __restrict__ x,
                                                   const float* __restrict__ pos,
                                                   const float* __restrict__ nrm,
                                                   const float* __restrict__ Wa,
                                                   const float* __restrict__ ba) {
    constexpr int TPN = C / 4;
    __shared__ __align__(16) float sW[CIN * C];
    __shared__ __align__(16) float sb[C];
    const int t = threadIdx.x;
    for (int i = t; i < CIN * C; i += 128) sW[i] = Wa[i];
    for (int i = t; i < C; i += 128) sb[i] = ba[i];
    __syncthreads();

    const int n  = blockIdx.x * (128 / TPN) + t / TPN;
    const int c0 = (t % TPN) * 4;
    float4 acc = *reinterpret_cast<const float4*>(&sb[c0]);
#pragma unroll
    for (int k = 0; k < CIN; ++k) {
        float xv;
        if (FIRST) xv = (k < 3) ? pos[n * 3 + k] : nrm[n * 3 + (k - 3)];
        else       xv = x[n * CIN + k];
        const float4 w = *reinterpret_cast<const float4*>(&sW[k * C + c0]);
        acc.x = fmaf(xv, w.x, acc.x);
        acc.y = fmaf(xv, w.y, acc.y);
        acc.z = fmaf(xv, w.z, acc.z);
        acc.w = fmaf(xv, w.w, acc.w);
    }
    *reinterpret_cast<float4*>(&g_A[n * C + c0]) = acc;
}

// ---------------------------------------------------------------------------
// Fused edge kernel (unchanged from R3-passing version).
// ---------------------------------------------------------------------------
template <int C, int G, int NPB>
__global__ void __launch_bounds__(2 * C) edge_kernel(
    const float* __restrict__ pos,
    const float* __restrict__ Wa, int cin_node,
    const float* __restrict__ gmm, const float* __restrict__ bta,
    const float* __restrict__ Wb,  const float* __restrict__ bb,
    float* __restrict__ out) {
    constexpr int B  = 2 * C;
    constexpr int HS = 20;
    constexpr int NG = 4;
    extern __shared__ float smem[];
    float* s_Wb   = smem;
    float* s_H    = s_Wb + C * C;
    float* s_Wrel = s_H + NG * C * HS;
    float* s_g    = s_Wrel + 3 * C;
    float* s_b    = s_g + C;
    float* s_bb   = s_b + C;

    const int t = threadIdx.x;
    for (int i = t; i < C * C; i += B) s_Wb[i] = Wb[i];
    for (int i = t; i < 3 * C; i += B) s_Wrel[i] = Wa[cin_node * C + i];
    for (int i = t; i < C; i += B) { s_g[i] = gmm[i]; s_b[i] = bta[i]; s_bb[i] = bb[i]; }
    __syncthreads();

    const int e    = t & 15;
    const int g    = t >> 4;
    const int lane = t & 31;
    const int w    = t >> 5;
    const int et   = lane & 3;
    const int fi   = lane >> 2;
    const int q3   = (C == 128) ? (w >> 1) : w;
    const int f0   = ((C == 128) ? (w & 1) * 64 : 0) + fi * 8;

    for (int s0 = 0; s0 < NPB; s0 += NG) {
#pragma unroll
        for (int q = 0; q < NG; ++q) {
            const int i = blockIdx.x * NPB + s0 + q;
            float* Hq = s_H + q * C * HS;
            const int j = g_nbr[i * KNB + e];
            const float rx = pos[j * 3 + 0] - pos[i * 3 + 0];
            const float ry = pos[j * 3 + 1] - pos[i * 3 + 1];
            const float rz = pos[j * 3 + 2] - pos[i * 3 + 2];
            const int c0 = g * 8;
            const float* Ar = g_A + j * C + c0;
            const float4 a0 = *reinterpret_cast<const float4*>(Ar);
            const float4 a1 = *reinterpret_cast<const float4*>(Ar + 4);
            float h[8] = {a0.x, a0.y, a0.z, a0.w, a1.x, a1.y, a1.z, a1.w};
            float sum = 0.f;
#pragma unroll
            for (int cc = 0; cc < 8; ++cc) {
                const int c = c0 + cc;
                h[cc] = h[cc] + rx * s_Wrel[c] + ry * s_Wrel[C + c] + rz * s_Wrel[2 * C + c];
                sum += h[cc];
            }
            const float mean = sum * 0.125f;
            float vs = 0.f;
#pragma unroll
            for (int cc = 0; cc < 8; ++cc) { const float d = h[cc] - mean; vs = fmaf(d, d, vs); }
            const float inv = rsqrtf(fmaf(vs, 0.125f, 1e-5f));
#pragma unroll
            for (int cc = 0; cc < 8; ++cc) {
                const int c = c0 + cc;
                const float vv = fmaf((h[cc] - mean) * inv, s_g[c], s_b[c]);
                Hq[c * HS + e] = fmaxf(vv, 0.f);
            }
        }
        __syncthreads();
        {
            const int i = blockIdx.x * NPB + s0 + q3;
            const float* Hq = s_H + q3 * C * HS;
            float acc[4][8];
#pragma unroll
            for (int a = 0; a < 4; ++a)
#pragma unroll
                for (int f = 0; f < 8; ++f) acc[a][f] = 0.f;

#pragma unroll 4
            for (int c = 0; c < C; ++c) {
                const float4 h4 = *reinterpret_cast<const float4*>(&Hq[c * HS + et * 4]);
                const float4 wa = *reinterpret_cast<const float4*>(&s_Wb[c * C + f0]);
                const float4 wc = *reinterpret_cast<const float4*>(&s_Wb[c * C + f0 + 4]);
                const float he[4] = {h4.x, h4.y, h4.z, h4.w};
                const float wf[8] = {wa.x, wa.y, wa.z, wa.w, wc.x, wc.y, wc.z, wc.w};
#pragma unroll
                for (int a = 0; a < 4; ++a)
#pragma unroll
                    for (int f = 0; f < 8; ++f)
                        acc[a][f] = fmaf(he[a], wf[f], acc[a][f]);
            }
            float m[8];
#pragma unroll
            for (int f = 0; f < 8; ++f) {
                m[f] = fmaxf(fmaxf(acc[0][f], acc[1][f]), fmaxf(acc[2][f], acc[3][f]));
                m[f] = fmaxf(m[f], __shfl_xor_sync(0xffffffffu, m[f], 1));
                m[f] = fmaxf(m[f], __shfl_xor_sync(0xffffffffu, m[f], 2));
            }
            if (et == 0) {
                float4 r0, r1;
                r0.x = fmaxf(m[0] + s_bb[f0 + 0], 0.f);
                r0.y = fmaxf(m[1] + s_bb[f0 + 1], 0.f);
                r0.z = fmaxf(m[2] + s_bb[f0 + 2], 0.f);
                r0.w = fmaxf(m[3] + s_bb[f0 + 3], 0.f);
                r1.x = fmaxf(m[4] + s_bb[f0 + 4], 0.f);
                r1.y = fmaxf(m[5] + s_bb[f0 + 5], 0.f);
                r1.z = fmaxf(m[6] + s_bb[f0 + 6], 0.f);
                r1.w = fmaxf(m[7] + s_bb[f0 + 7], 0.f);
                *reinterpret_cast<float4*>(&out[i * C + f0])     = r0;
                *reinterpret_cast<float4*>(&out[i * C + f0 + 4]) = r1;
            }
        }
        __syncthreads();
    }
}

// ---------------------------------------------------------------------------
extern "C" void kernel_launch(void* const* d_in, const int* in_sizes, int n_in,
                              void* d_out, int out_size) {
    const float* pos    = (const float*)d_in[0];
    const float* normal = (const float*)d_in[1];
    const float* W1a = (const float*)d_in[2];
    const float* b1a = (const float*)d_in[3];
    const float* g1  = (const float*)d_in[4];
    const float* be1 = (const float*)d_in[5];
    const float* W1b = (const float*)d_in[6];
    const float* b1b = (const float*)d_in[7];
    const float* W2a = (const float*)d_in[8];
    const float* b2a = (const float*)d_in[9];
    const float* g2  = (const float*)d_in[10];
    const float* be2 = (const float*)d_in[11];
    const float* W2b = (const float*)d_in[12];
    const float* b2b = (const float*)d_in[13];
    const float* W3a = (const float*)d_in[14];
    const float* b3a = (const float*)d_in[15];
    const float* g3  = (const float*)d_in[16];
    const float* be3 = (const float*)d_in[17];
    const float* W3b = (const float*)d_in[18];
    const float* b3b = (const float*)d_in[19];

    float* out = (float*)d_out;
    float* h1 = out;
    float* h2 = out + NPTS * 64;
    float* h3 = out + NPTS * 128;

    const int SMEM64  = (64 * 64  + 4 * 64 * 20  + 3 * 64  + 3 * 64)  * 4;
    const int SMEM128 = (128 * 128 + 4 * 128 * 20 + 3 * 128 + 3 * 128) * 4;
    cudaFuncSetAttribute((const void*)edge_kernel<64, 8, 8>,
                         cudaFuncAttributeMaxDynamicSharedMemorySize, SMEM64);
    cudaFuncSetAttribute((const void*)edge_kernel<128, 16, 8>,
                         cudaFuncAttributeMaxDynamicSharedMemorySize, SMEM128);

    pos4_kernel<<<NPTS / 256, 256>>>(pos);
    knn_kernel<<<NPTS / WPB, 32 * WPB>>>();

    proj_kernel<6, 64, true><<<NPTS / 8, 128>>>(nullptr, pos, normal, W1a, b1a);
    edge_kernel<64, 8, 8><<<NPTS / 8, 128, SMEM64>>>(pos, W1a, 6, g1, be1, W1b, b1b, h1);

    proj_kernel<64, 64, false><<<NPTS / 8, 128>>>(h1, nullptr, nullptr, W2a, b2a);
    edge_kernel<64, 8, 8><<<NPTS / 8, 128, SMEM64>>>(pos, W2a, 64, g2, be2, W2b, b2b, h2);

    proj_kernel<64, 128, false><<<NPTS / 4, 128>>>(h2, nullptr, nullptr, W3a, b3a);
    edge_kernel<128, 16, 8><<<NPTS / 8, 256, SMEM128>>>(pos, W3a, 64, g3, be3, W3b, b3b, h3);
}